// round 2
// baseline (speedup 1.0000x reference)
#include <cuda_runtime.h>
#include <stdint.h>

// Problem constants
#define KB 2
#define KS 2048
#define KDM 1024
#define KH 16
#define KD 64
#define KSCALE 0.125f
#define KMASKFILL -1000000000.0f

// Scratch: Q/K/V in [b][h][s][d] layout (16 MB each)
__device__ float g_q[KB * KH * KS * KD];
__device__ float g_k[KB * KH * KS * KD];
__device__ float g_v[KB * KH * KS * KD];

// ---------------------------------------------------------------------------
// Kernel 1: QKV projection GEMM.
// qkv[m, n] = sum_k x[m, k] * W[n, k],  m = b*2048+s (4096), n (3072), k (1024)
// Output scattered to g_q/g_k/g_v as [b][h][s][d].
// 64x64 tile, BK=16, 256 threads, 4x4 register blocking.
// ---------------------------------------------------------------------------
__global__ __launch_bounds__(256) void qkv_gemm_kernel(
    const float* __restrict__ x, const float* __restrict__ w) {
    __shared__ float As[16][64];  // [k][m]
    __shared__ float Bs[16][64];  // [k][n]

    const int tid = threadIdx.x;
    const int m0 = blockIdx.y * 64;
    const int n0 = blockIdx.x * 64;

    // Load assignment: row (m or n) in low lane bits -> <=2-way smem store conflict
    const int rlo = tid & 15;
    const int slo = (tid >> 4) & 3;   // k-segment (float4) 0..3
    const int rhi = tid >> 6;
    const int row = rlo + (rhi << 4); // 0..63

    const int ty = tid >> 4;  // 0..15 -> m sub-tile
    const int tx = tid & 15;  // 0..15 -> n sub-tile

    const float* xg = x + (size_t)(m0 + row) * KDM + slo * 4;
    const float* wg = w + (size_t)(n0 + row) * KDM + slo * 4;

    float c[4][4] = {};

    for (int k0 = 0; k0 < KDM; k0 += 16) {
        float4 a4 = *(const float4*)(xg + k0);
        float4 b4 = *(const float4*)(wg + k0);
        __syncthreads();  // previous iteration done reading smem
        As[slo * 4 + 0][row] = a4.x;
        As[slo * 4 + 1][row] = a4.y;
        As[slo * 4 + 2][row] = a4.z;
        As[slo * 4 + 3][row] = a4.w;
        Bs[slo * 4 + 0][row] = b4.x;
        Bs[slo * 4 + 1][row] = b4.y;
        Bs[slo * 4 + 2][row] = b4.z;
        Bs[slo * 4 + 3][row] = b4.w;
        __syncthreads();
#pragma unroll
        for (int kk = 0; kk < 16; ++kk) {
            float4 av = *(const float4*)&As[kk][ty * 4];
            float4 bv = *(const float4*)&Bs[kk][tx * 4];
            c[0][0] += av.x * bv.x; c[0][1] += av.x * bv.y;
            c[0][2] += av.x * bv.z; c[0][3] += av.x * bv.w;
            c[1][0] += av.y * bv.x; c[1][1] += av.y * bv.y;
            c[1][2] += av.y * bv.z; c[1][3] += av.y * bv.w;
            c[2][0] += av.z * bv.x; c[2][1] += av.z * bv.y;
            c[2][2] += av.z * bv.z; c[2][3] += av.z * bv.w;
            c[3][0] += av.w * bv.x; c[3][1] += av.w * bv.y;
            c[3][2] += av.w * bv.z; c[3][3] += av.w * bv.w;
        }
    }

    // n0 is 64-aligned so whole tile maps to one (three, h); d = tx*4+j
    const int three = n0 >> 10;
    const int h = (n0 >> 6) & 15;
    float* dst = (three == 0) ? g_q : (three == 1) ? g_k : g_v;
#pragma unroll
    for (int i = 0; i < 4; ++i) {
        int m = m0 + ty * 4 + i;
        int bb = m >> 11;
        int ss = m & 2047;
        float4 r = make_float4(c[i][0], c[i][1], c[i][2], c[i][3]);
        *(float4*)(dst + ((size_t)((bb * KH + h) * KS + ss)) * KD + tx * 4) = r;
    }
}

// ---------------------------------------------------------------------------
// Kernel 2: flash-style attention.
// One CTA per (b, h, 64-query tile). Loops 32 key tiles of 64.
// out[b, q, h*64+d] = softmax_k(mask ? q.k*scale : -1e9) @ V
// Mask is read as uint32 (nonzero = true): robust to bool widened to either
// int32 (1) or float32 (1.0f) by the harness.
// ---------------------------------------------------------------------------
__global__ __launch_bounds__(256) void flash_kernel(
    const uint32_t* __restrict__ mask, float* __restrict__ out) {
    __shared__ float Qt[64][64];  // [d][q]
    __shared__ float KP[64][64];  // Kt [d][k] during scores; P [q][k] after
    __shared__ float Vs[64][64];  // [k][d]

    const int tid = threadIdx.x;
    const int qt = blockIdx.x;
    const int h = blockIdx.y;
    const int b = blockIdx.z;

    const int rlo = tid & 15;
    const int slo = (tid >> 4) & 3;
    const int rhi = tid >> 6;
    const int row = rlo + (rhi << 4);

    const int ty = tid >> 4;
    const int tx = tid & 15;

    const float* Qg = g_q + ((size_t)(b * KH + h) * KS + qt * 64) * KD;

    // Load Q tile transposed into Qt[d][q]
#pragma unroll
    for (int r = 0; r < 4; ++r) {
        int seg = slo + r * 4;
        float4 v4 = *(const float4*)(Qg + row * KD + seg * 4);
        Qt[seg * 4 + 0][row] = v4.x;
        Qt[seg * 4 + 1][row] = v4.y;
        Qt[seg * 4 + 2][row] = v4.z;
        Qt[seg * 4 + 3][row] = v4.w;
    }

    float o[4][4] = {};
    float m_r[4], l_r[4];
#pragma unroll
    for (int i = 0; i < 4; ++i) {
        m_r[i] = __int_as_float(0xff800000);  // -inf
        l_r[i] = 0.0f;
    }

    const int q0 = qt * 64 + ty * 4;

    for (int kt = 0; kt < KS / 64; ++kt) {
        const float* Kg = g_k + ((size_t)(b * KH + h) * KS + kt * 64) * KD;
        const float* Vg = g_v + ((size_t)(b * KH + h) * KS + kt * 64) * KD;

        __syncthreads();  // previous PV done reading KP / Vs
#pragma unroll
        for (int r = 0; r < 4; ++r) {
            int seg = slo + r * 4;
            float4 k4 = *(const float4*)(Kg + row * KD + seg * 4);
            KP[seg * 4 + 0][row] = k4.x;
            KP[seg * 4 + 1][row] = k4.y;
            KP[seg * 4 + 2][row] = k4.z;
            KP[seg * 4 + 3][row] = k4.w;
            float4 v4 = *(const float4*)(Vg + row * KD + seg * 4);
            *(float4*)&Vs[row][seg * 4] = v4;
        }
        __syncthreads();

        // Scores: s[i][j] = Q[q0+i] . K[k0+j]
        float s[4][4] = {};
#pragma unroll 16
        for (int kk = 0; kk < 64; ++kk) {
            float4 av = *(const float4*)&Qt[kk][ty * 4];
            float4 bv = *(const float4*)&KP[kk][tx * 4];
            s[0][0] += av.x * bv.x; s[0][1] += av.x * bv.y;
            s[0][2] += av.x * bv.z; s[0][3] += av.x * bv.w;
            s[1][0] += av.y * bv.x; s[1][1] += av.y * bv.y;
            s[1][2] += av.y * bv.z; s[1][3] += av.y * bv.w;
            s[2][0] += av.z * bv.x; s[2][1] += av.z * bv.y;
            s[2][2] += av.z * bv.z; s[2][3] += av.z * bv.w;
            s[3][0] += av.w * bv.x; s[3][1] += av.w * bv.y;
            s[3][2] += av.w * bv.z; s[3][3] += av.w * bv.w;
        }

        // Scale + mask (mask[b][q][h][key], 4-byte elements, nonzero = keep)
        const int k0 = kt * 64 + tx * 4;
#pragma unroll
        for (int i = 0; i < 4; ++i) {
            const uint32_t* mp =
                mask + (((size_t)(b * KS + (q0 + i)) * KH + h) * KS + k0);
            uint4 mm = *(const uint4*)mp;
            s[i][0] = mm.x ? s[i][0] * KSCALE : KMASKFILL;
            s[i][1] = mm.y ? s[i][1] * KSCALE : KMASKFILL;
            s[i][2] = mm.z ? s[i][2] * KSCALE : KMASKFILL;
            s[i][3] = mm.w ? s[i][3] * KSCALE : KMASKFILL;
        }

        // Online softmax (rows live in 16-lane groups: same ty, tx 0..15)
#pragma unroll
        for (int i = 0; i < 4; ++i) {
            float tm = fmaxf(fmaxf(s[i][0], s[i][1]), fmaxf(s[i][2], s[i][3]));
            tm = fmaxf(tm, __shfl_xor_sync(0xffffffffu, tm, 1));
            tm = fmaxf(tm, __shfl_xor_sync(0xffffffffu, tm, 2));
            tm = fmaxf(tm, __shfl_xor_sync(0xffffffffu, tm, 4));
            tm = fmaxf(tm, __shfl_xor_sync(0xffffffffu, tm, 8));
            float mn = fmaxf(m_r[i], tm);
            float corr = __expf(m_r[i] - mn);  // expf(-inf) = 0 on first tile
            m_r[i] = mn;
            float p0 = __expf(s[i][0] - mn);
            float p1 = __expf(s[i][1] - mn);
            float p2 = __expf(s[i][2] - mn);
            float p3 = __expf(s[i][3] - mn);
            float ps = p0 + p1 + p2 + p3;
            ps += __shfl_xor_sync(0xffffffffu, ps, 1);
            ps += __shfl_xor_sync(0xffffffffu, ps, 2);
            ps += __shfl_xor_sync(0xffffffffu, ps, 4);
            ps += __shfl_xor_sync(0xffffffffu, ps, 8);
            l_r[i] = l_r[i] * corr + ps;
            o[i][0] *= corr; o[i][1] *= corr; o[i][2] *= corr; o[i][3] *= corr;
            s[i][0] = p0; s[i][1] = p1; s[i][2] = p2; s[i][3] = p3;
        }

        __syncthreads();  // everyone done reading KP (K tile)
        // Store P tile [q][k] into KP
#pragma unroll
        for (int i = 0; i < 4; ++i) {
            *(float4*)&KP[ty * 4 + i][tx * 4] =
                make_float4(s[i][0], s[i][1], s[i][2], s[i][3]);
        }
        __syncthreads();

        // PV: o[i][j] += sum_kk P[q][kk] * V[kk][d]
#pragma unroll 16
        for (int kk = 0; kk < 64; ++kk) {
            float4 vv = *(const float4*)&Vs[kk][tx * 4];
            float a0 = KP[ty * 4 + 0][kk];
            float a1 = KP[ty * 4 + 1][kk];
            float a2 = KP[ty * 4 + 2][kk];
            float a3 = KP[ty * 4 + 3][kk];
            o[0][0] += a0 * vv.x; o[0][1] += a0 * vv.y;
            o[0][2] += a0 * vv.z; o[0][3] += a0 * vv.w;
            o[1][0] += a1 * vv.x; o[1][1] += a1 * vv.y;
            o[1][2] += a1 * vv.z; o[1][3] += a1 * vv.w;
            o[2][0] += a2 * vv.x; o[2][1] += a2 * vv.y;
            o[2][2] += a2 * vv.z; o[2][3] += a2 * vv.w;
            o[3][0] += a3 * vv.x; o[3][1] += a3 * vv.y;
            o[3][2] += a3 * vv.z; o[3][3] += a3 * vv.w;
        }
    }

    // Epilogue: normalize and write out[b, q, h*64 + d]
#pragma unroll
    for (int i = 0; i < 4; ++i) {
        int q = q0 + i;
        float inv = 1.0f / l_r[i];
        float4 r = make_float4(o[i][0] * inv, o[i][1] * inv,
                               o[i][2] * inv, o[i][3] * inv);
        *(float4*)(out + (size_t)(b * KS + q) * KDM + h * KD + tx * 4) = r;
    }
}

extern "C" void kernel_launch(void* const* d_in, const int* in_sizes, int n_in,
                              void* d_out, int out_size) {
    const float* x = (const float*)d_in[0];
    const float* w = (const float*)d_in[1];
    const uint32_t* mask = (const uint32_t*)d_in[2];
    float* out = (float*)d_out;

    dim3 g1(3 * KDM / 64, KB * KS / 64);  // (48, 64)
    qkv_gemm_kernel<<<g1, 256>>>(x, w);

    dim3 g2(KS / 64, KH, KB);  // (32, 16, 2)
    flash_kernel<<<g2, 256>>>(mask, out);
}

// round 4
// speedup vs baseline: 1.3545x; 1.3545x over previous
#include <cuda_runtime.h>
#include <cuda_bf16.h>
#include <stdint.h>

// Problem constants
#define KB 2
#define KS 2048
#define KDM 1024
#define KH 16
#define KD 64
#define KSCALE 0.125f
#define KMASKFILL -1000000000.0f

// Scratch: Q/K/V in [b][h][s][d] layout (16 MB each)
__device__ float g_q[KB * KH * KS * KD];
__device__ float g_k[KB * KH * KS * KD];
__device__ float g_v[KB * KH * KS * KD];

__device__ __forceinline__ uint32_t smem_u32(const void* p) {
    uint32_t a;
    asm("{ .reg .u64 t; cvta.to.shared.u64 t, %1; cvt.u32.u64 %0, t; }"
        : "=r"(a) : "l"(p));
    return a;
}

__device__ __forceinline__ void ldmx4(uint32_t& r0, uint32_t& r1, uint32_t& r2,
                                      uint32_t& r3, uint32_t addr) {
    asm volatile("ldmatrix.sync.aligned.m8n8.x4.shared.b16 {%0,%1,%2,%3}, [%4];"
                 : "=r"(r0), "=r"(r1), "=r"(r2), "=r"(r3) : "r"(addr));
}

__device__ __forceinline__ void mma_bf16(float* c, const uint32_t* a,
                                         const uint32_t* b) {
    asm volatile(
        "mma.sync.aligned.m16n8k16.row.col.f32.bf16.bf16.f32 "
        "{%0,%1,%2,%3}, {%4,%5,%6,%7}, {%8,%9}, {%0,%1,%2,%3};"
        : "+f"(c[0]), "+f"(c[1]), "+f"(c[2]), "+f"(c[3])
        : "r"(a[0]), "r"(a[1]), "r"(a[2]), "r"(a[3]), "r"(b[0]), "r"(b[1]));
}

__device__ __forceinline__ uint32_t pack_hi(float a, float b) {
    return (uint32_t)__bfloat16_as_ushort(__float2bfloat16(a)) |
           ((uint32_t)__bfloat16_as_ushort(__float2bfloat16(b)) << 16);
}
__device__ __forceinline__ uint32_t pack_lo(float a, float b) {
    float ra = a - __bfloat162float(__float2bfloat16(a));
    float rb = b - __bfloat162float(__float2bfloat16(b));
    return (uint32_t)__bfloat16_as_ushort(__float2bfloat16(ra)) |
           ((uint32_t)__bfloat16_as_ushort(__float2bfloat16(rb)) << 16);
}

// ---------------------------------------------------------------------------
// Kernel 1: QKV projection via mma.sync bf16 hi/lo split.
// C[m,n] = sum_k x[m,k] * W[n,k] = Ahi*Bhi + Ahi*Blo + Alo*Bhi (fp32 acc).
// CTA: 128x128 tile, BK=32, 256 threads (8 warps, 4x2: each 32x64).
// Smem: 4 tiles (Ahi,Alo,Bhi,Blo) 128 rows x 32 bf16, 80B stride (conflict-free
// ldmatrix). fp32->bf16 split happens during the smem store.
// ---------------------------------------------------------------------------
#define ROWB 80
__global__ __launch_bounds__(256) void qkv_mma_kernel(
    const float* __restrict__ x, const float* __restrict__ w) {
    __shared__ char st[4][128 * ROWB];  // Ahi, Alo, Bhi, Blo

    const int tid = threadIdx.x;
    const int lane = tid & 31;
    const int wid = tid >> 5;
    const int wm = wid & 3;   // 4 warps over M (32 rows each)
    const int wn = wid >> 2;  // 2 warps over N (64 cols each)
    const int m0 = blockIdx.y * 128;
    const int n0 = blockIdx.x * 128;

    const uint32_t sA_hi = smem_u32(st[0]);
    const uint32_t sA_lo = smem_u32(st[1]);
    const uint32_t sB_hi = smem_u32(st[2]);
    const uint32_t sB_lo = smem_u32(st[3]);

    // Load assignment: 1024 float4 chunks per operand, 4 per thread
    const int lrow = tid >> 1;          // rows 0..127 (2 threads/row)
    const int lch0 = (tid & 1) * 4;     // float4 chunk 0..7 (4 consecutive)
    const float* xg = x + (size_t)(m0 + lrow) * KDM + lch0 * 4;
    const float* wg = w + (size_t)(n0 + lrow) * KDM + lch0 * 4;

    float acc[2][8][4] = {};
    float4 ra[4], rb[4];

    // Prefetch stage 0
#pragma unroll
    for (int t = 0; t < 4; ++t) {
        ra[t] = *(const float4*)(xg + t * 4);
        rb[t] = *(const float4*)(wg + t * 4);
    }

    for (int s = 0; s < KDM / 32; ++s) {
        // Store + convert current stage regs into smem
        {
            uint32_t off = lrow * ROWB + lch0 * 8;
#pragma unroll
            for (int t = 0; t < 4; ++t) {
                uint2 h, l;
                h.x = pack_hi(ra[t].x, ra[t].y);
                h.y = pack_hi(ra[t].z, ra[t].w);
                l.x = pack_lo(ra[t].x, ra[t].y);
                l.y = pack_lo(ra[t].z, ra[t].w);
                *(uint2*)(st[0] + off + t * 8) = h;
                *(uint2*)(st[1] + off + t * 8) = l;
                h.x = pack_hi(rb[t].x, rb[t].y);
                h.y = pack_hi(rb[t].z, rb[t].w);
                l.x = pack_lo(rb[t].x, rb[t].y);
                l.y = pack_lo(rb[t].z, rb[t].w);
                *(uint2*)(st[2] + off + t * 8) = h;
                *(uint2*)(st[3] + off + t * 8) = l;
            }
        }
        __syncthreads();

        // Prefetch next stage
        if (s + 1 < KDM / 32) {
            const float* xn = xg + (s + 1) * 32;
            const float* wn_ = wg + (s + 1) * 32;
#pragma unroll
            for (int t = 0; t < 4; ++t) {
                ra[t] = *(const float4*)(xn + t * 4);
                rb[t] = *(const float4*)(wn_ + t * 4);
            }
        }

        // Compute 2 k-steps of 16
        const int q = lane >> 3, roff = lane & 7;
#pragma unroll
        for (int ks = 0; ks < 2; ++ks) {
            uint32_t ahi[2][4], alo[2][4], bhi[8][2], blo[8][2];
            // A fragments: TL/BL/TR/BR ldmatrix ordering
            const uint32_t aoff =
                (uint32_t)(wm * 32 + (q & 1) * 8 + roff) * ROWB +
                (ks * 16 + (q >> 1) * 8) * 2;
#pragma unroll
            for (int mt = 0; mt < 2; ++mt) {
                ldmx4(ahi[mt][0], ahi[mt][1], ahi[mt][2], ahi[mt][3],
                      sA_hi + aoff + mt * 16 * ROWB);
                ldmx4(alo[mt][0], alo[mt][1], alo[mt][2], alo[mt][3],
                      sA_lo + aoff + mt * 16 * ROWB);
            }
            // B fragments: pairs of n-tiles per ldmatrix.x4
            const uint32_t boff =
                (uint32_t)(wn * 64 + (q >> 1) * 8 + roff) * ROWB +
                (ks * 16 + (q & 1) * 8) * 2;
#pragma unroll
            for (int p = 0; p < 4; ++p) {
                ldmx4(bhi[2 * p][0], bhi[2 * p][1], bhi[2 * p + 1][0],
                      bhi[2 * p + 1][1], sB_hi + boff + p * 16 * ROWB);
                ldmx4(blo[2 * p][0], blo[2 * p][1], blo[2 * p + 1][0],
                      blo[2 * p + 1][1], sB_lo + boff + p * 16 * ROWB);
            }
#pragma unroll
            for (int mt = 0; mt < 2; ++mt)
#pragma unroll
                for (int nt = 0; nt < 8; ++nt) {
                    mma_bf16(acc[mt][nt], ahi[mt], bhi[nt]);
                    mma_bf16(acc[mt][nt], ahi[mt], blo[nt]);
                    mma_bf16(acc[mt][nt], alo[mt], bhi[nt]);
                }
        }
        __syncthreads();
    }

    // Epilogue: scatter accumulators to g_q / g_k / g_v
#pragma unroll
    for (int mt = 0; mt < 2; ++mt) {
#pragma unroll
        for (int nt = 0; nt < 8; ++nt) {
            int n = n0 + wn * 64 + nt * 8 + (lane & 3) * 2;
            int three = n >> 10;
            int h = (n >> 6) & 15;
            int d = n & 63;
            float* dst = (three == 0) ? g_q : (three == 1) ? g_k : g_v;
            int m = m0 + wm * 32 + mt * 16 + (lane >> 2);
            int bb = m >> 11, ss = m & 2047;
            float* p0 = dst + ((size_t)(bb * KH + h) * KS + ss) * KD + d;
            *(float2*)p0 = make_float2(acc[mt][nt][0], acc[mt][nt][1]);
            float* p1 = p0 + 8 * KD;  // m + 8
            *(float2*)p1 = make_float2(acc[mt][nt][2], acc[mt][nt][3]);
        }
    }
}

// ---------------------------------------------------------------------------
// Kernel 2: flash-style attention (fp32, unchanged from R2).
// ---------------------------------------------------------------------------
__global__ __launch_bounds__(256) void flash_kernel(
    const uint32_t* __restrict__ mask, float* __restrict__ out) {
    __shared__ float Qt[64][64];
    __shared__ float KP[64][64];
    __shared__ float Vs[64][64];

    const int tid = threadIdx.x;
    const int qt = blockIdx.x;
    const int h = blockIdx.y;
    const int b = blockIdx.z;

    const int rlo = tid & 15;
    const int slo = (tid >> 4) & 3;
    const int rhi = tid >> 6;
    const int row = rlo + (rhi << 4);

    const int ty = tid >> 4;
    const int tx = tid & 15;

    const float* Qg = g_q + ((size_t)(b * KH + h) * KS + qt * 64) * KD;

#pragma unroll
    for (int r = 0; r < 4; ++r) {
        int seg = slo + r * 4;
        float4 v4 = *(const float4*)(Qg + row * KD + seg * 4);
        Qt[seg * 4 + 0][row] = v4.x;
        Qt[seg * 4 + 1][row] = v4.y;
        Qt[seg * 4 + 2][row] = v4.z;
        Qt[seg * 4 + 3][row] = v4.w;
    }

    float o[4][4] = {};
    float m_r[4], l_r[4];
#pragma unroll
    for (int i = 0; i < 4; ++i) {
        m_r[i] = __int_as_float(0xff800000);
        l_r[i] = 0.0f;
    }

    const int q0 = qt * 64 + ty * 4;

    for (int kt = 0; kt < KS / 64; ++kt) {
        const float* Kg = g_k + ((size_t)(b * KH + h) * KS + kt * 64) * KD;
        const float* Vg = g_v + ((size_t)(b * KH + h) * KS + kt * 64) * KD;

        __syncthreads();
#pragma unroll
        for (int r = 0; r < 4; ++r) {
            int seg = slo + r * 4;
            float4 k4 = *(const float4*)(Kg + row * KD + seg * 4);
            KP[seg * 4 + 0][row] = k4.x;
            KP[seg * 4 + 1][row] = k4.y;
            KP[seg * 4 + 2][row] = k4.z;
            KP[seg * 4 + 3][row] = k4.w;
            float4 v4 = *(const float4*)(Vg + row * KD + seg * 4);
            *(float4*)&Vs[row][seg * 4] = v4;
        }
        __syncthreads();

        float s[4][4] = {};
#pragma unroll 16
        for (int kk = 0; kk < 64; ++kk) {
            float4 av = *(const float4*)&Qt[kk][ty * 4];
            float4 bv = *(const float4*)&KP[kk][tx * 4];
            s[0][0] += av.x * bv.x; s[0][1] += av.x * bv.y;
            s[0][2] += av.x * bv.z; s[0][3] += av.x * bv.w;
            s[1][0] += av.y * bv.x; s[1][1] += av.y * bv.y;
            s[1][2] += av.y * bv.z; s[1][3] += av.y * bv.w;
            s[2][0] += av.z * bv.x; s[2][1] += av.z * bv.y;
            s[2][2] += av.z * bv.z; s[2][3] += av.z * bv.w;
            s[3][0] += av.w * bv.x; s[3][1] += av.w * bv.y;
            s[3][2] += av.w * bv.z; s[3][3] += av.w * bv.w;
        }

        const int k0 = kt * 64 + tx * 4;
#pragma unroll
        for (int i = 0; i < 4; ++i) {
            const uint32_t* mp =
                mask + (((size_t)(b * KS + (q0 + i)) * KH + h) * KS + k0);
            uint4 mm = *(const uint4*)mp;
            s[i][0] = mm.x ? s[i][0] * KSCALE : KMASKFILL;
            s[i][1] = mm.y ? s[i][1] * KSCALE : KMASKFILL;
            s[i][2] = mm.z ? s[i][2] * KSCALE : KMASKFILL;
            s[i][3] = mm.w ? s[i][3] * KSCALE : KMASKFILL;
        }

#pragma unroll
        for (int i = 0; i < 4; ++i) {
            float tm = fmaxf(fmaxf(s[i][0], s[i][1]), fmaxf(s[i][2], s[i][3]));
            tm = fmaxf(tm, __shfl_xor_sync(0xffffffffu, tm, 1));
            tm = fmaxf(tm, __shfl_xor_sync(0xffffffffu, tm, 2));
            tm = fmaxf(tm, __shfl_xor_sync(0xffffffffu, tm, 4));
            tm = fmaxf(tm, __shfl_xor_sync(0xffffffffu, tm, 8));
            float mn = fmaxf(m_r[i], tm);
            float corr = __expf(m_r[i] - mn);
            m_r[i] = mn;
            float p0 = __expf(s[i][0] - mn);
            float p1 = __expf(s[i][1] - mn);
            float p2 = __expf(s[i][2] - mn);
            float p3 = __expf(s[i][3] - mn);
            float ps = p0 + p1 + p2 + p3;
            ps += __shfl_xor_sync(0xffffffffu, ps, 1);
            ps += __shfl_xor_sync(0xffffffffu, ps, 2);
            ps += __shfl_xor_sync(0xffffffffu, ps, 4);
            ps += __shfl_xor_sync(0xffffffffu, ps, 8);
            l_r[i] = l_r[i] * corr + ps;
            o[i][0] *= corr; o[i][1] *= corr; o[i][2] *= corr; o[i][3] *= corr;
            s[i][0] = p0; s[i][1] = p1; s[i][2] = p2; s[i][3] = p3;
        }

        __syncthreads();
#pragma unroll
        for (int i = 0; i < 4; ++i) {
            *(float4*)&KP[ty * 4 + i][tx * 4] =
                make_float4(s[i][0], s[i][1], s[i][2], s[i][3]);
        }
        __syncthreads();

#pragma unroll 16
        for (int kk = 0; kk < 64; ++kk) {
            float4 vv = *(const float4*)&Vs[kk][tx * 4];
            float a0 = KP[ty * 4 + 0][kk];
            float a1 = KP[ty * 4 + 1][kk];
            float a2 = KP[ty * 4 + 2][kk];
            float a3 = KP[ty * 4 + 3][kk];
            o[0][0] += a0 * vv.x; o[0][1] += a0 * vv.y;
            o[0][2] += a0 * vv.z; o[0][3] += a0 * vv.w;
            o[1][0] += a1 * vv.x; o[1][1] += a1 * vv.y;
            o[1][2] += a1 * vv.z; o[1][3] += a1 * vv.w;
            o[2][0] += a2 * vv.x; o[2][1] += a2 * vv.y;
            o[2][2] += a2 * vv.z; o[2][3] += a2 * vv.w;
            o[3][0] += a3 * vv.x; o[3][1] += a3 * vv.y;
            o[3][2] += a3 * vv.z; o[3][3] += a3 * vv.w;
        }
    }

#pragma unroll
    for (int i = 0; i < 4; ++i) {
        int q = q0 + i;
        float inv = 1.0f / l_r[i];
        float4 r = make_float4(o[i][0] * inv, o[i][1] * inv,
                               o[i][2] * inv, o[i][3] * inv);
        *(float4*)(out + (size_t)(b * KS + q) * KDM + h * KD + tx * 4) = r;
    }
}

extern "C" void kernel_launch(void* const* d_in, const int* in_sizes, int n_in,
                              void* d_out, int out_size) {
    const float* x = (const float*)d_in[0];
    const float* w = (const float*)d_in[1];
    const uint32_t* mask = (const uint32_t*)d_in[2];
    float* out = (float*)d_out;

    dim3 g1(3 * KDM / 128, KB * KS / 128);  // (24, 32)
    qkv_mma_kernel<<<g1, 256>>>(x, w);

    dim3 g2(KS / 64, KH, KB);  // (32, 16, 2)
    flash_kernel<<<g2, 256>>>(mask, out);
}

// round 5
// speedup vs baseline: 2.5892x; 1.9115x over previous
#include <cuda_runtime.h>
#include <cuda_bf16.h>
#include <stdint.h>

// Problem constants
#define KB 2
#define KS 2048
#define KDM 1024
#define KH 16
#define KD 64
#define KSCALE 0.125f
#define KMASKFILL -1000000000.0f

// Scratch: bf16 hi/lo split Q/K/V in [b][h][s][d] (Q pre-scaled by KSCALE)
__device__ __nv_bfloat16 g_qhi[KB * KH * KS * KD];
__device__ __nv_bfloat16 g_qlo[KB * KH * KS * KD];
__device__ __nv_bfloat16 g_khi[KB * KH * KS * KD];
__device__ __nv_bfloat16 g_klo[KB * KH * KS * KD];
__device__ __nv_bfloat16 g_vhi[KB * KH * KS * KD];
__device__ __nv_bfloat16 g_vlo[KB * KH * KS * KD];

__device__ __forceinline__ uint32_t smem_u32(const void* p) {
    uint32_t a;
    asm("{ .reg .u64 t; cvta.to.shared.u64 t, %1; cvt.u32.u64 %0, t; }"
        : "=r"(a) : "l"(p));
    return a;
}

__device__ __forceinline__ void ldmx4(uint32_t& r0, uint32_t& r1, uint32_t& r2,
                                      uint32_t& r3, uint32_t addr) {
    asm volatile("ldmatrix.sync.aligned.m8n8.x4.shared.b16 {%0,%1,%2,%3}, [%4];"
                 : "=r"(r0), "=r"(r1), "=r"(r2), "=r"(r3) : "r"(addr));
}

__device__ __forceinline__ void ldmx4t(uint32_t& r0, uint32_t& r1, uint32_t& r2,
                                       uint32_t& r3, uint32_t addr) {
    asm volatile(
        "ldmatrix.sync.aligned.m8n8.x4.trans.shared.b16 {%0,%1,%2,%3}, [%4];"
        : "=r"(r0), "=r"(r1), "=r"(r2), "=r"(r3) : "r"(addr));
}

__device__ __forceinline__ void mma_bf16(float* c, const uint32_t* a,
                                         const uint32_t* b) {
    asm volatile(
        "mma.sync.aligned.m16n8k16.row.col.f32.bf16.bf16.f32 "
        "{%0,%1,%2,%3}, {%4,%5,%6,%7}, {%8,%9}, {%0,%1,%2,%3};"
        : "+f"(c[0]), "+f"(c[1]), "+f"(c[2]), "+f"(c[3])
        : "r"(a[0]), "r"(a[1]), "r"(a[2]), "r"(a[3]), "r"(b[0]), "r"(b[1]));
}

__device__ __forceinline__ uint32_t pack_hi(float a, float b) {
    return (uint32_t)__bfloat16_as_ushort(__float2bfloat16(a)) |
           ((uint32_t)__bfloat16_as_ushort(__float2bfloat16(b)) << 16);
}
__device__ __forceinline__ uint32_t pack_lo(float a, float b) {
    float ra = a - __bfloat162float(__float2bfloat16(a));
    float rb = b - __bfloat162float(__float2bfloat16(b));
    return (uint32_t)__bfloat16_as_ushort(__float2bfloat16(ra)) |
           ((uint32_t)__bfloat16_as_ushort(__float2bfloat16(rb)) << 16);
}

// ---------------------------------------------------------------------------
// Kernel 1: QKV projection via mma.sync bf16 hi/lo split.
// C[m,n] = sum_k x[m,k] * W[n,k] = Ahi*Bhi + Ahi*Blo + Alo*Bhi (fp32 acc).
// Epilogue: split fp32 result into bf16 hi/lo arrays (Q scaled by KSCALE).
// ---------------------------------------------------------------------------
#define ROWB 80
__global__ __launch_bounds__(256) void qkv_mma_kernel(
    const float* __restrict__ x, const float* __restrict__ w) {
    __shared__ char st[4][128 * ROWB];  // Ahi, Alo, Bhi, Blo

    const int tid = threadIdx.x;
    const int lane = tid & 31;
    const int wid = tid >> 5;
    const int wm = wid & 3;
    const int wn = wid >> 2;
    const int m0 = blockIdx.y * 128;
    const int n0 = blockIdx.x * 128;

    const uint32_t sA_hi = smem_u32(st[0]);
    const uint32_t sA_lo = smem_u32(st[1]);
    const uint32_t sB_hi = smem_u32(st[2]);
    const uint32_t sB_lo = smem_u32(st[3]);

    const int lrow = tid >> 1;
    const int lch0 = (tid & 1) * 4;
    const float* xg = x + (size_t)(m0 + lrow) * KDM + lch0 * 4;
    const float* wg = w + (size_t)(n0 + lrow) * KDM + lch0 * 4;

    float acc[2][8][4] = {};
    float4 ra[4], rb[4];

#pragma unroll
    for (int t = 0; t < 4; ++t) {
        ra[t] = *(const float4*)(xg + t * 4);
        rb[t] = *(const float4*)(wg + t * 4);
    }

    for (int s = 0; s < KDM / 32; ++s) {
        {
            uint32_t off = lrow * ROWB + lch0 * 8;
#pragma unroll
            for (int t = 0; t < 4; ++t) {
                uint2 h, l;
                h.x = pack_hi(ra[t].x, ra[t].y);
                h.y = pack_hi(ra[t].z, ra[t].w);
                l.x = pack_lo(ra[t].x, ra[t].y);
                l.y = pack_lo(ra[t].z, ra[t].w);
                *(uint2*)(st[0] + off + t * 8) = h;
                *(uint2*)(st[1] + off + t * 8) = l;
                h.x = pack_hi(rb[t].x, rb[t].y);
                h.y = pack_hi(rb[t].z, rb[t].w);
                l.x = pack_lo(rb[t].x, rb[t].y);
                l.y = pack_lo(rb[t].z, rb[t].w);
                *(uint2*)(st[2] + off + t * 8) = h;
                *(uint2*)(st[3] + off + t * 8) = l;
            }
        }
        __syncthreads();

        if (s + 1 < KDM / 32) {
            const float* xn = xg + (s + 1) * 32;
            const float* wn_ = wg + (s + 1) * 32;
#pragma unroll
            for (int t = 0; t < 4; ++t) {
                ra[t] = *(const float4*)(xn + t * 4);
                rb[t] = *(const float4*)(wn_ + t * 4);
            }
        }

        const int q = lane >> 3, roff = lane & 7;
#pragma unroll
        for (int ks = 0; ks < 2; ++ks) {
            uint32_t ahi[2][4], alo[2][4], bhi[8][2], blo[8][2];
            const uint32_t aoff =
                (uint32_t)(wm * 32 + (q & 1) * 8 + roff) * ROWB +
                (ks * 16 + (q >> 1) * 8) * 2;
#pragma unroll
            for (int mt = 0; mt < 2; ++mt) {
                ldmx4(ahi[mt][0], ahi[mt][1], ahi[mt][2], ahi[mt][3],
                      sA_hi + aoff + mt * 16 * ROWB);
                ldmx4(alo[mt][0], alo[mt][1], alo[mt][2], alo[mt][3],
                      sA_lo + aoff + mt * 16 * ROWB);
            }
            const uint32_t boff =
                (uint32_t)(wn * 64 + (q >> 1) * 8 + roff) * ROWB +
                (ks * 16 + (q & 1) * 8) * 2;
#pragma unroll
            for (int p = 0; p < 4; ++p) {
                ldmx4(bhi[2 * p][0], bhi[2 * p][1], bhi[2 * p + 1][0],
                      bhi[2 * p + 1][1], sB_hi + boff + p * 16 * ROWB);
                ldmx4(blo[2 * p][0], blo[2 * p][1], blo[2 * p + 1][0],
                      blo[2 * p + 1][1], sB_lo + boff + p * 16 * ROWB);
            }
#pragma unroll
            for (int mt = 0; mt < 2; ++mt)
#pragma unroll
                for (int nt = 0; nt < 8; ++nt) {
                    mma_bf16(acc[mt][nt], ahi[mt], bhi[nt]);
                    mma_bf16(acc[mt][nt], ahi[mt], blo[nt]);
                    mma_bf16(acc[mt][nt], alo[mt], bhi[nt]);
                }
        }
        __syncthreads();
    }

    // Epilogue: bf16 hi/lo split scatter (Q gets KSCALE folded in)
#pragma unroll
    for (int mt = 0; mt < 2; ++mt) {
#pragma unroll
        for (int nt = 0; nt < 8; ++nt) {
            int n = n0 + wn * 64 + nt * 8 + (lane & 3) * 2;
            int three = n >> 10;
            int h = (n >> 6) & 15;
            int d = n & 63;
            __nv_bfloat16* dhi =
                (three == 0) ? g_qhi : (three == 1) ? g_khi : g_vhi;
            __nv_bfloat16* dlo =
                (three == 0) ? g_qlo : (three == 1) ? g_klo : g_vlo;
            float sc = (three == 0) ? KSCALE : 1.0f;
            int m = m0 + wm * 32 + mt * 16 + (lane >> 2);
            int bb = m >> 11, ss = m & 2047;
            size_t off = ((size_t)(bb * KH + h) * KS + ss) * KD + d;
            float v0 = acc[mt][nt][0] * sc, v1 = acc[mt][nt][1] * sc;
            *(uint32_t*)(dhi + off) = pack_hi(v0, v1);
            *(uint32_t*)(dlo + off) = pack_lo(v0, v1);
            float v2 = acc[mt][nt][2] * sc, v3 = acc[mt][nt][3] * sc;
            *(uint32_t*)(dhi + off + 8 * KD) = pack_hi(v2, v3);
            *(uint32_t*)(dlo + off + 8 * KD) = pack_lo(v2, v3);
        }
    }
}

// ---------------------------------------------------------------------------
// Kernel 2: flash attention via mma.sync bf16 hi/lo split.
// CTA: 4 warps, 64 queries; loop over 32 key tiles of 64. d = 64.
// S-fragment registers are reused directly as P A-fragments (no smem trip).
// ---------------------------------------------------------------------------
#define FROWB 144
__global__ __launch_bounds__(128) void flash_mma_kernel(
    const uint32_t* __restrict__ mask, float* __restrict__ out) {
    __shared__ char sKhi[64 * FROWB], sKlo[64 * FROWB];
    __shared__ char sVhi[64 * FROWB], sVlo[64 * FROWB];

    const int tid = threadIdx.x;
    const int lane = tid & 31;
    const int w = tid >> 5;
    const int qt = blockIdx.x;
    const int h = blockIdx.y;
    const int b = blockIdx.z;
    const int q0 = qt * 64;

    const uint32_t sKhiA = smem_u32(sKhi);
    const uint32_t sKloA = smem_u32(sKlo);
    const uint32_t sVhiA = smem_u32(sVhi);
    const uint32_t sVloA = smem_u32(sVlo);

    const size_t headoff = ((size_t)(b * KH + h) * KS) * KD;

    // Prologue: load Q tile (hi/lo) into sKhi/sKlo, ldmatrix into registers
#pragma unroll
    for (int t = 0; t < 4; ++t) {
        int idx = tid + t * 128;
        int row = idx >> 3, seg = idx & 7;
        uint32_t so = row * FROWB + seg * 16;
        size_t go = headoff + (size_t)(q0 + row) * KD + seg * 8;
        *(uint4*)(sKhi + so) = *(const uint4*)(g_qhi + go);
        *(uint4*)(sKlo + so) = *(const uint4*)(g_qlo + go);
    }
    __syncthreads();

    uint32_t qfh[4][4], qfl[4][4];
    {
        int arow = 16 * w + (lane & 7) + ((lane >> 3) & 1) * 8;
#pragma unroll
        for (int t = 0; t < 4; ++t) {
            uint32_t off = (uint32_t)arow * FROWB + t * 32 + (lane >> 4) * 16;
            ldmx4(qfh[t][0], qfh[t][1], qfh[t][2], qfh[t][3], sKhiA + off);
            ldmx4(qfl[t][0], qfl[t][1], qfl[t][2], qfl[t][3], sKloA + off);
        }
    }
    __syncthreads();

    const int rq = lane >> 2, cq = lane & 3;
    const int bB_row = (lane & 7) + ((lane >> 4) & 1) * 8;  // K (QK) ldmatrix
    const int bB_seg = (lane >> 3) & 1;
    const int vB_row = (lane & 7) + ((lane >> 3) & 1) * 8;  // V (trans) ldmatrix
    const int vB_seg = (lane >> 4) & 1;

    float o[8][4] = {};
    float m0 = __int_as_float(0xff800000), m1 = m0;
    float l0 = 0.0f, l1 = 0.0f;

    const uint32_t* mr0 =
        mask + ((size_t)(b * KS + q0 + 16 * w + rq) * KH + h) * KS + 2 * cq;
    const uint32_t* mr1 = mr0 + (size_t)8 * KH * KS;

    for (int kt = 0; kt < KS / 64; ++kt) {
        // Load K/V hi/lo tiles
#pragma unroll
        for (int t = 0; t < 4; ++t) {
            int idx = tid + t * 128;
            int row = idx >> 3, seg = idx & 7;
            uint32_t so = row * FROWB + seg * 16;
            size_t go = headoff + (size_t)(kt * 64 + row) * KD + seg * 8;
            *(uint4*)(sKhi + so) = *(const uint4*)(g_khi + go);
            *(uint4*)(sKlo + so) = *(const uint4*)(g_klo + go);
            *(uint4*)(sVhi + so) = *(const uint4*)(g_vhi + go);
            *(uint4*)(sVlo + so) = *(const uint4*)(g_vlo + go);
        }
        __syncthreads();

        // S = Q . K^T (3-pass hi/lo)
        float s[8][4] = {};
#pragma unroll
        for (int t = 0; t < 4; ++t) {
            uint32_t bh[8][2], bl[8][2];
#pragma unroll
            for (int jp = 0; jp < 4; ++jp) {
                uint32_t off = (uint32_t)(16 * jp + bB_row) * FROWB +
                               (2 * t + bB_seg) * 16;
                ldmx4(bh[2 * jp][0], bh[2 * jp][1], bh[2 * jp + 1][0],
                      bh[2 * jp + 1][1], sKhiA + off);
                ldmx4(bl[2 * jp][0], bl[2 * jp][1], bl[2 * jp + 1][0],
                      bl[2 * jp + 1][1], sKloA + off);
            }
#pragma unroll
            for (int j = 0; j < 8; ++j) {
                mma_bf16(s[j], qfh[t], bh[j]);
                mma_bf16(s[j], qfh[t], bl[j]);
                mma_bf16(s[j], qfl[t], bh[j]);
            }
        }

        // Mask (scale already folded into Q)
        const uint32_t* mk0 = mr0 + kt * 64;
        const uint32_t* mk1 = mr1 + kt * 64;
#pragma unroll
        for (int j = 0; j < 8; ++j) {
            uint2 a = *(const uint2*)(mk0 + 8 * j);
            s[j][0] = a.x ? s[j][0] : KMASKFILL;
            s[j][1] = a.y ? s[j][1] : KMASKFILL;
            uint2 c = *(const uint2*)(mk1 + 8 * j);
            s[j][2] = c.x ? s[j][2] : KMASKFILL;
            s[j][3] = c.y ? s[j][3] : KMASKFILL;
        }

        // Online softmax for the two rows this thread owns (rq, rq+8)
        float t0 = __int_as_float(0xff800000), t1 = t0;
#pragma unroll
        for (int j = 0; j < 8; ++j) {
            t0 = fmaxf(t0, fmaxf(s[j][0], s[j][1]));
            t1 = fmaxf(t1, fmaxf(s[j][2], s[j][3]));
        }
        t0 = fmaxf(t0, __shfl_xor_sync(0xffffffffu, t0, 1));
        t0 = fmaxf(t0, __shfl_xor_sync(0xffffffffu, t0, 2));
        t1 = fmaxf(t1, __shfl_xor_sync(0xffffffffu, t1, 1));
        t1 = fmaxf(t1, __shfl_xor_sync(0xffffffffu, t1, 2));
        float mn0 = fmaxf(m0, t0), mn1 = fmaxf(m1, t1);
        float c0 = __expf(m0 - mn0), c1 = __expf(m1 - mn1);
        m0 = mn0;
        m1 = mn1;
        float rs0 = 0.0f, rs1 = 0.0f;
#pragma unroll
        for (int j = 0; j < 8; ++j) {
            s[j][0] = __expf(s[j][0] - mn0);
            s[j][1] = __expf(s[j][1] - mn0);
            s[j][2] = __expf(s[j][2] - mn1);
            s[j][3] = __expf(s[j][3] - mn1);
            rs0 += s[j][0] + s[j][1];
            rs1 += s[j][2] + s[j][3];
        }
        rs0 += __shfl_xor_sync(0xffffffffu, rs0, 1);
        rs0 += __shfl_xor_sync(0xffffffffu, rs0, 2);
        rs1 += __shfl_xor_sync(0xffffffffu, rs1, 1);
        rs1 += __shfl_xor_sync(0xffffffffu, rs1, 2);
        l0 = l0 * c0 + rs0;
        l1 = l1 * c1 + rs1;
#pragma unroll
        for (int nd = 0; nd < 8; ++nd) {
            o[nd][0] *= c0;
            o[nd][1] *= c0;
            o[nd][2] *= c1;
            o[nd][3] *= c1;
        }

        // P fragments (S C-frag layout == P A-frag layout), hi/lo split
        uint32_t ph[4][4], pl[4][4];
#pragma unroll
        for (int t = 0; t < 4; ++t) {
            ph[t][0] = pack_hi(s[2 * t][0], s[2 * t][1]);
            ph[t][1] = pack_hi(s[2 * t][2], s[2 * t][3]);
            ph[t][2] = pack_hi(s[2 * t + 1][0], s[2 * t + 1][1]);
            ph[t][3] = pack_hi(s[2 * t + 1][2], s[2 * t + 1][3]);
            pl[t][0] = pack_lo(s[2 * t][0], s[2 * t][1]);
            pl[t][1] = pack_lo(s[2 * t][2], s[2 * t][3]);
            pl[t][2] = pack_lo(s[2 * t + 1][0], s[2 * t + 1][1]);
            pl[t][3] = pack_lo(s[2 * t + 1][2], s[2 * t + 1][3]);
        }

        // O += P . V (3-pass hi/lo), V via ldmatrix.trans
#pragma unroll
        for (int t = 0; t < 4; ++t) {
            uint32_t vh[8][2], vl[8][2];
#pragma unroll
            for (int np = 0; np < 4; ++np) {
                uint32_t off = (uint32_t)(16 * t + vB_row) * FROWB +
                               (2 * np + vB_seg) * 16;
                ldmx4t(vh[2 * np][0], vh[2 * np][1], vh[2 * np + 1][0],
                       vh[2 * np + 1][1], sVhiA + off);
                ldmx4t(vl[2 * np][0], vl[2 * np][1], vl[2 * np + 1][0],
                       vl[2 * np + 1][1], sVloA + off);
            }
#pragma unroll
            for (int nd = 0; nd < 8; ++nd) {
                mma_bf16(o[nd], ph[t], vh[nd]);
                mma_bf16(o[nd], ph[t], vl[nd]);
                mma_bf16(o[nd], pl[t], vh[nd]);
            }
        }
        __syncthreads();
    }

    // Epilogue
    float inv0 = 1.0f / l0, inv1 = 1.0f / l1;
    const int row0 = q0 + 16 * w + rq;
#pragma unroll
    for (int nd = 0; nd < 8; ++nd) {
        int d = 8 * nd + 2 * cq;
        float* p0 = out + (size_t)(b * KS + row0) * KDM + h * KD + d;
        *(float2*)p0 = make_float2(o[nd][0] * inv0, o[nd][1] * inv0);
        float* p1 = p0 + (size_t)8 * KDM;
        *(float2*)p1 = make_float2(o[nd][2] * inv1, o[nd][3] * inv1);
    }
}

extern "C" void kernel_launch(void* const* d_in, const int* in_sizes, int n_in,
                              void* d_out, int out_size) {
    const float* x = (const float*)d_in[0];
    const float* w = (const float*)d_in[1];
    const uint32_t* mask = (const uint32_t*)d_in[2];
    float* out = (float*)d_out;

    dim3 g1(3 * KDM / 128, KB * KS / 128);  // (24, 32)
    qkv_mma_kernel<<<g1, 256>>>(x, w);

    dim3 g2(KS / 64, KH, KB);  // (32, 16, 2)
    flash_mma_kernel<<<g2, 128>>>(mask, out);
}

// round 6
// speedup vs baseline: 2.7614x; 1.0665x over previous
#include <cuda_runtime.h>
#include <cuda_bf16.h>
#include <stdint.h>

// Problem constants
#define KB 2
#define KS 2048
#define KDM 1024
#define KH 16
#define KD 64
#define KSCALE 0.125f
#define KMASKFILL -1000000000.0f

// Scratch: bf16 hi/lo split Q/K/V in [b][h][s][d] (Q pre-scaled by KSCALE)
__device__ __nv_bfloat16 g_qhi[KB * KH * KS * KD];
__device__ __nv_bfloat16 g_qlo[KB * KH * KS * KD];
__device__ __nv_bfloat16 g_khi[KB * KH * KS * KD];
__device__ __nv_bfloat16 g_klo[KB * KH * KS * KD];
__device__ __nv_bfloat16 g_vhi[KB * KH * KS * KD];
__device__ __nv_bfloat16 g_vlo[KB * KH * KS * KD];

__device__ __forceinline__ uint32_t smem_u32(const void* p) {
    uint32_t a;
    asm("{ .reg .u64 t; cvta.to.shared.u64 t, %1; cvt.u32.u64 %0, t; }"
        : "=r"(a) : "l"(p));
    return a;
}

__device__ __forceinline__ void ldmx4(uint32_t& r0, uint32_t& r1, uint32_t& r2,
                                      uint32_t& r3, uint32_t addr) {
    asm volatile("ldmatrix.sync.aligned.m8n8.x4.shared.b16 {%0,%1,%2,%3}, [%4];"
                 : "=r"(r0), "=r"(r1), "=r"(r2), "=r"(r3) : "r"(addr));
}

__device__ __forceinline__ void ldmx4t(uint32_t& r0, uint32_t& r1, uint32_t& r2,
                                       uint32_t& r3, uint32_t addr) {
    asm volatile(
        "ldmatrix.sync.aligned.m8n8.x4.trans.shared.b16 {%0,%1,%2,%3}, [%4];"
        : "=r"(r0), "=r"(r1), "=r"(r2), "=r"(r3) : "r"(addr));
}

__device__ __forceinline__ void mma_bf16(float* c, const uint32_t* a,
                                         const uint32_t* b) {
    asm volatile(
        "mma.sync.aligned.m16n8k16.row.col.f32.bf16.bf16.f32 "
        "{%0,%1,%2,%3}, {%4,%5,%6,%7}, {%8,%9}, {%0,%1,%2,%3};"
        : "+f"(c[0]), "+f"(c[1]), "+f"(c[2]), "+f"(c[3])
        : "r"(a[0]), "r"(a[1]), "r"(a[2]), "r"(a[3]), "r"(b[0]), "r"(b[1]));
}

__device__ __forceinline__ void cpasync16(uint32_t saddr, const void* g) {
    asm volatile("cp.async.cg.shared.global [%0], [%1], 16;"
                 :: "r"(saddr), "l"(g) : "memory");
}
__device__ __forceinline__ void cpa_commit() {
    asm volatile("cp.async.commit_group;" ::: "memory");
}
__device__ __forceinline__ void cpa_wait1() {
    asm volatile("cp.async.wait_group 1;" ::: "memory");
}

__device__ __forceinline__ uint32_t pack_hi(float a, float b) {
    return (uint32_t)__bfloat16_as_ushort(__float2bfloat16(a)) |
           ((uint32_t)__bfloat16_as_ushort(__float2bfloat16(b)) << 16);
}
__device__ __forceinline__ uint32_t pack_lo(float a, float b) {
    float ra = a - __bfloat162float(__float2bfloat16(a));
    float rb = b - __bfloat162float(__float2bfloat16(b));
    return (uint32_t)__bfloat16_as_ushort(__float2bfloat16(ra)) |
           ((uint32_t)__bfloat16_as_ushort(__float2bfloat16(rb)) << 16);
}

// ---------------------------------------------------------------------------
// Kernel 1: QKV projection via mma.sync bf16 hi/lo split (unchanged from R4).
// ---------------------------------------------------------------------------
#define ROWB 80
__global__ __launch_bounds__(256) void qkv_mma_kernel(
    const float* __restrict__ x, const float* __restrict__ w) {
    __shared__ char st[4][128 * ROWB];  // Ahi, Alo, Bhi, Blo

    const int tid = threadIdx.x;
    const int lane = tid & 31;
    const int wid = tid >> 5;
    const int wm = wid & 3;
    const int wn = wid >> 2;
    const int m0 = blockIdx.y * 128;
    const int n0 = blockIdx.x * 128;

    const uint32_t sA_hi = smem_u32(st[0]);
    const uint32_t sA_lo = smem_u32(st[1]);
    const uint32_t sB_hi = smem_u32(st[2]);
    const uint32_t sB_lo = smem_u32(st[3]);

    const int lrow = tid >> 1;
    const int lch0 = (tid & 1) * 4;
    const float* xg = x + (size_t)(m0 + lrow) * KDM + lch0 * 4;
    const float* wg = w + (size_t)(n0 + lrow) * KDM + lch0 * 4;

    float acc[2][8][4] = {};
    float4 ra[4], rb[4];

#pragma unroll
    for (int t = 0; t < 4; ++t) {
        ra[t] = *(const float4*)(xg + t * 4);
        rb[t] = *(const float4*)(wg + t * 4);
    }

    for (int s = 0; s < KDM / 32; ++s) {
        {
            uint32_t off = lrow * ROWB + lch0 * 8;
#pragma unroll
            for (int t = 0; t < 4; ++t) {
                uint2 h, l;
                h.x = pack_hi(ra[t].x, ra[t].y);
                h.y = pack_hi(ra[t].z, ra[t].w);
                l.x = pack_lo(ra[t].x, ra[t].y);
                l.y = pack_lo(ra[t].z, ra[t].w);
                *(uint2*)(st[0] + off + t * 8) = h;
                *(uint2*)(st[1] + off + t * 8) = l;
                h.x = pack_hi(rb[t].x, rb[t].y);
                h.y = pack_hi(rb[t].z, rb[t].w);
                l.x = pack_lo(rb[t].x, rb[t].y);
                l.y = pack_lo(rb[t].z, rb[t].w);
                *(uint2*)(st[2] + off + t * 8) = h;
                *(uint2*)(st[3] + off + t * 8) = l;
            }
        }
        __syncthreads();

        if (s + 1 < KDM / 32) {
            const float* xn = xg + (s + 1) * 32;
            const float* wn_ = wg + (s + 1) * 32;
#pragma unroll
            for (int t = 0; t < 4; ++t) {
                ra[t] = *(const float4*)(xn + t * 4);
                rb[t] = *(const float4*)(wn_ + t * 4);
            }
        }

        const int q = lane >> 3, roff = lane & 7;
#pragma unroll
        for (int ks = 0; ks < 2; ++ks) {
            uint32_t ahi[2][4], alo[2][4], bhi[8][2], blo[8][2];
            const uint32_t aoff =
                (uint32_t)(wm * 32 + (q & 1) * 8 + roff) * ROWB +
                (ks * 16 + (q >> 1) * 8) * 2;
#pragma unroll
            for (int mt = 0; mt < 2; ++mt) {
                ldmx4(ahi[mt][0], ahi[mt][1], ahi[mt][2], ahi[mt][3],
                      sA_hi + aoff + mt * 16 * ROWB);
                ldmx4(alo[mt][0], alo[mt][1], alo[mt][2], alo[mt][3],
                      sA_lo + aoff + mt * 16 * ROWB);
            }
            const uint32_t boff =
                (uint32_t)(wn * 64 + (q >> 1) * 8 + roff) * ROWB +
                (ks * 16 + (q & 1) * 8) * 2;
#pragma unroll
            for (int p = 0; p < 4; ++p) {
                ldmx4(bhi[2 * p][0], bhi[2 * p][1], bhi[2 * p + 1][0],
                      bhi[2 * p + 1][1], sB_hi + boff + p * 16 * ROWB);
                ldmx4(blo[2 * p][0], blo[2 * p][1], blo[2 * p + 1][0],
                      blo[2 * p + 1][1], sB_lo + boff + p * 16 * ROWB);
            }
#pragma unroll
            for (int mt = 0; mt < 2; ++mt)
#pragma unroll
                for (int nt = 0; nt < 8; ++nt) {
                    mma_bf16(acc[mt][nt], ahi[mt], bhi[nt]);
                    mma_bf16(acc[mt][nt], ahi[mt], blo[nt]);
                    mma_bf16(acc[mt][nt], alo[mt], bhi[nt]);
                }
        }
        __syncthreads();
    }

#pragma unroll
    for (int mt = 0; mt < 2; ++mt) {
#pragma unroll
        for (int nt = 0; nt < 8; ++nt) {
            int n = n0 + wn * 64 + nt * 8 + (lane & 3) * 2;
            int three = n >> 10;
            int h = (n >> 6) & 15;
            int d = n & 63;
            __nv_bfloat16* dhi =
                (three == 0) ? g_qhi : (three == 1) ? g_khi : g_vhi;
            __nv_bfloat16* dlo =
                (three == 0) ? g_qlo : (three == 1) ? g_klo : g_vlo;
            float sc = (three == 0) ? KSCALE : 1.0f;
            int m = m0 + wm * 32 + mt * 16 + (lane >> 2);
            int bb = m >> 11, ss = m & 2047;
            size_t off = ((size_t)(bb * KH + h) * KS + ss) * KD + d;
            float v0 = acc[mt][nt][0] * sc, v1 = acc[mt][nt][1] * sc;
            *(uint32_t*)(dhi + off) = pack_hi(v0, v1);
            *(uint32_t*)(dlo + off) = pack_lo(v0, v1);
            float v2 = acc[mt][nt][2] * sc, v3 = acc[mt][nt][3] * sc;
            *(uint32_t*)(dhi + off + 8 * KD) = pack_hi(v2, v3);
            *(uint32_t*)(dlo + off + 8 * KD) = pack_lo(v2, v3);
        }
    }
}

// ---------------------------------------------------------------------------
// Kernel 2: flash attention, mma.sync bf16 hi/lo + cp.async double buffering.
// CTA: 4 warps, 64 queries; 32 key tiles of 64; 2-stage cp.async pipeline.
// ---------------------------------------------------------------------------
#define FROWB 144
#define FTILE (64 * FROWB)   // 9216 B per array
#define FSTAGE (4 * FTILE)   // Khi,Klo,Vhi,Vlo = 36864 B per stage
#define FSMEM (2 * FSTAGE)   // 73728 B dynamic smem
#define FNT (KS / 64)

__global__ __launch_bounds__(128, 3) void flash_mma_kernel(
    const uint32_t* __restrict__ mask, float* __restrict__ out) {
    extern __shared__ char fsm[];
    const uint32_t dynb = smem_u32(fsm);

    const int tid = threadIdx.x;
    const int lane = tid & 31;
    const int w = tid >> 5;
    const int qt = blockIdx.x;
    const int h = blockIdx.y;
    const int b = blockIdx.z;
    const int q0 = qt * 64;

    const size_t headoff = ((size_t)(b * KH + h) * KS) * KD;

    // Prologue: stage Q (hi/lo) through stage-0 smem, ldmatrix into registers
#pragma unroll
    for (int t = 0; t < 4; ++t) {
        int idx = tid + t * 128;
        int row = idx >> 3, seg = idx & 7;
        uint32_t so = row * FROWB + seg * 16;
        size_t go = headoff + (size_t)(q0 + row) * KD + seg * 8;
        *(uint4*)(fsm + so) = *(const uint4*)(g_qhi + go);
        *(uint4*)(fsm + FTILE + so) = *(const uint4*)(g_qlo + go);
    }
    __syncthreads();

    uint32_t qfh[4][4], qfl[4][4];
    {
        int arow = 16 * w + (lane & 7) + ((lane >> 3) & 1) * 8;
#pragma unroll
        for (int t = 0; t < 4; ++t) {
            uint32_t off = (uint32_t)arow * FROWB + t * 32 + (lane >> 4) * 16;
            ldmx4(qfh[t][0], qfh[t][1], qfh[t][2], qfh[t][3], dynb + off);
            ldmx4(qfl[t][0], qfl[t][1], qfl[t][2], qfl[t][3],
                  dynb + FTILE + off);
        }
    }
    __syncthreads();

    // Per-tile cp.async issue (16B x 16 per thread = full 32KB stage)
    const int crow = (tid + 0 * 128) >> 3;  // base row pattern; per-t below
    (void)crow;
#define ISSUE_TILE(kt, buf)                                                   \
    {                                                                         \
        _Pragma("unroll") for (int t = 0; t < 4; ++t) {                       \
            int idx = tid + t * 128;                                          \
            int row = idx >> 3, seg = idx & 7;                                \
            uint32_t so = dynb + (buf) * FSTAGE + row * FROWB + seg * 16;     \
            size_t go = headoff + (size_t)((kt) * 64 + row) * KD + seg * 8;   \
            cpasync16(so, g_khi + go);                                        \
            cpasync16(so + FTILE, g_klo + go);                                \
            cpasync16(so + 2 * FTILE, g_vhi + go);                            \
            cpasync16(so + 3 * FTILE, g_vlo + go);                            \
        }                                                                     \
    }

    ISSUE_TILE(0, 0);
    cpa_commit();
    ISSUE_TILE(1, 1);
    cpa_commit();

    const int rq = lane >> 2, cq = lane & 3;
    const int bB_row = (lane & 7) + ((lane >> 4) & 1) * 8;
    const int bB_seg = (lane >> 3) & 1;
    const int vB_row = (lane & 7) + ((lane >> 3) & 1) * 8;
    const int vB_seg = (lane >> 4) & 1;

    float o[8][4] = {};
    float m0 = __int_as_float(0xff800000), m1 = m0;
    float l0 = 0.0f, l1 = 0.0f;

    const uint32_t* mr0 =
        mask + ((size_t)(b * KS + q0 + 16 * w + rq) * KH + h) * KS + 2 * cq;
    const uint32_t* mr1 = mr0 + (size_t)8 * KH * KS;

    for (int kt = 0; kt < FNT; ++kt) {
        cpa_wait1();
        __syncthreads();

        const uint32_t sK = dynb + (kt & 1) * FSTAGE;
        const uint32_t sKl = sK + FTILE;
        const uint32_t sV = sK + 2 * FTILE;
        const uint32_t sVl = sK + 3 * FTILE;

        // Mask prefetch, packed into one predicate word (bits 4j..4j+3)
        const uint32_t* mk0 = mr0 + kt * 64;
        const uint32_t* mk1 = mr1 + kt * 64;
        uint32_t mbits = 0;
#pragma unroll
        for (int j = 0; j < 8; ++j) {
            uint2 a = *(const uint2*)(mk0 + 8 * j);
            uint2 c = *(const uint2*)(mk1 + 8 * j);
            mbits |= (a.x ? 1u : 0u) << (4 * j);
            mbits |= (a.y ? 2u : 0u) << (4 * j);
            mbits |= (c.x ? 4u : 0u) << (4 * j);
            mbits |= (c.y ? 8u : 0u) << (4 * j);
        }

        // S = Q . K^T (3-pass hi/lo)
        float s[8][4] = {};
#pragma unroll
        for (int t = 0; t < 4; ++t) {
            uint32_t bh[8][2], bl[8][2];
#pragma unroll
            for (int jp = 0; jp < 4; ++jp) {
                uint32_t off = (uint32_t)(16 * jp + bB_row) * FROWB +
                               (2 * t + bB_seg) * 16;
                ldmx4(bh[2 * jp][0], bh[2 * jp][1], bh[2 * jp + 1][0],
                      bh[2 * jp + 1][1], sK + off);
                ldmx4(bl[2 * jp][0], bl[2 * jp][1], bl[2 * jp + 1][0],
                      bl[2 * jp + 1][1], sKl + off);
            }
#pragma unroll
            for (int j = 0; j < 8; ++j) {
                mma_bf16(s[j], qfh[t], bh[j]);
                mma_bf16(s[j], qfh[t], bl[j]);
                mma_bf16(s[j], qfl[t], bh[j]);
            }
        }

        // Apply mask
#pragma unroll
        for (int j = 0; j < 8; ++j) {
            uint32_t mj = mbits >> (4 * j);
            s[j][0] = (mj & 1) ? s[j][0] : KMASKFILL;
            s[j][1] = (mj & 2) ? s[j][1] : KMASKFILL;
            s[j][2] = (mj & 4) ? s[j][2] : KMASKFILL;
            s[j][3] = (mj & 8) ? s[j][3] : KMASKFILL;
        }

        // Online softmax (rows rq, rq+8 of this warp's 16-row block)
        float t0 = __int_as_float(0xff800000), t1 = t0;
#pragma unroll
        for (int j = 0; j < 8; ++j) {
            t0 = fmaxf(t0, fmaxf(s[j][0], s[j][1]));
            t1 = fmaxf(t1, fmaxf(s[j][2], s[j][3]));
        }
        t0 = fmaxf(t0, __shfl_xor_sync(0xffffffffu, t0, 1));
        t0 = fmaxf(t0, __shfl_xor_sync(0xffffffffu, t0, 2));
        t1 = fmaxf(t1, __shfl_xor_sync(0xffffffffu, t1, 1));
        t1 = fmaxf(t1, __shfl_xor_sync(0xffffffffu, t1, 2));
        float mn0 = fmaxf(m0, t0), mn1 = fmaxf(m1, t1);
        float c0 = __expf(m0 - mn0), c1 = __expf(m1 - mn1);
        m0 = mn0;
        m1 = mn1;
        float rs0 = 0.0f, rs1 = 0.0f;
#pragma unroll
        for (int j = 0; j < 8; ++j) {
            s[j][0] = __expf(s[j][0] - mn0);
            s[j][1] = __expf(s[j][1] - mn0);
            s[j][2] = __expf(s[j][2] - mn1);
            s[j][3] = __expf(s[j][3] - mn1);
            rs0 += s[j][0] + s[j][1];
            rs1 += s[j][2] + s[j][3];
        }
        rs0 += __shfl_xor_sync(0xffffffffu, rs0, 1);
        rs0 += __shfl_xor_sync(0xffffffffu, rs0, 2);
        rs1 += __shfl_xor_sync(0xffffffffu, rs1, 1);
        rs1 += __shfl_xor_sync(0xffffffffu, rs1, 2);
        l0 = l0 * c0 + rs0;
        l1 = l1 * c1 + rs1;
#pragma unroll
        for (int nd = 0; nd < 8; ++nd) {
            o[nd][0] *= c0;
            o[nd][1] *= c0;
            o[nd][2] *= c1;
            o[nd][3] *= c1;
        }

        // P fragments (S C-frag layout == P A-frag layout), hi/lo split
        uint32_t ph[4][4], pl[4][4];
#pragma unroll
        for (int t = 0; t < 4; ++t) {
            ph[t][0] = pack_hi(s[2 * t][0], s[2 * t][1]);
            ph[t][1] = pack_hi(s[2 * t][2], s[2 * t][3]);
            ph[t][2] = pack_hi(s[2 * t + 1][0], s[2 * t + 1][1]);
            ph[t][3] = pack_hi(s[2 * t + 1][2], s[2 * t + 1][3]);
            pl[t][0] = pack_lo(s[2 * t][0], s[2 * t][1]);
            pl[t][1] = pack_lo(s[2 * t][2], s[2 * t][3]);
            pl[t][2] = pack_lo(s[2 * t + 1][0], s[2 * t + 1][1]);
            pl[t][3] = pack_lo(s[2 * t + 1][2], s[2 * t + 1][3]);
        }

        // O += P . V (3-pass hi/lo), V via ldmatrix.trans
#pragma unroll
        for (int t = 0; t < 4; ++t) {
            uint32_t vh[8][2], vl[8][2];
#pragma unroll
            for (int np = 0; np < 4; ++np) {
                uint32_t off = (uint32_t)(16 * t + vB_row) * FROWB +
                               (2 * np + vB_seg) * 16;
                ldmx4t(vh[2 * np][0], vh[2 * np][1], vh[2 * np + 1][0],
                       vh[2 * np + 1][1], sV + off);
                ldmx4t(vl[2 * np][0], vl[2 * np][1], vl[2 * np + 1][0],
                       vl[2 * np + 1][1], sVl + off);
            }
#pragma unroll
            for (int nd = 0; nd < 8; ++nd) {
                mma_bf16(o[nd], ph[t], vh[nd]);
                mma_bf16(o[nd], ph[t], vl[nd]);
                mma_bf16(o[nd], pl[t], vh[nd]);
            }
        }
        __syncthreads();

        // Refill the buffer just consumed with tile kt+2
        if (kt + 2 < FNT) ISSUE_TILE(kt + 2, kt & 1);
        cpa_commit();
    }

    // Epilogue
    float inv0 = 1.0f / l0, inv1 = 1.0f / l1;
    const int row0 = q0 + 16 * w + rq;
#pragma unroll
    for (int nd = 0; nd < 8; ++nd) {
        int d = 8 * nd + 2 * cq;
        float* p0 = out + (size_t)(b * KS + row0) * KDM + h * KD + d;
        *(float2*)p0 = make_float2(o[nd][0] * inv0, o[nd][1] * inv0);
        float* p1 = p0 + (size_t)8 * KDM;
        *(float2*)p1 = make_float2(o[nd][2] * inv1, o[nd][3] * inv1);
    }
}

extern "C" void kernel_launch(void* const* d_in, const int* in_sizes, int n_in,
                              void* d_out, int out_size) {
    const float* x = (const float*)d_in[0];
    const float* w = (const float*)d_in[1];
    const uint32_t* mask = (const uint32_t*)d_in[2];
    float* out = (float*)d_out;

    cudaFuncSetAttribute(flash_mma_kernel,
                         cudaFuncAttributeMaxDynamicSharedMemorySize, FSMEM);

    dim3 g1(3 * KDM / 128, KB * KS / 128);  // (24, 32)
    qkv_mma_kernel<<<g1, 256>>>(x, w);

    dim3 g2(KS / 64, KH, KB);  // (32, 16, 2)
    flash_mma_kernel<<<g2, 128, FSMEM>>>(mask, out);
}

// round 7
// speedup vs baseline: 3.1133x; 1.1274x over previous
#include <cuda_runtime.h>
#include <cuda_bf16.h>
#include <stdint.h>

// Problem constants
#define KB 2
#define KS 2048
#define KDM 1024
#define KH 16
#define KD 64
#define KSCALE 0.125f
#define KMASKFILL -1000000000.0f

// Scratch: bf16 hi/lo split inputs and Q/K/V
__device__ __nv_bfloat16 g_xhi[KB * KS * KDM];
__device__ __nv_bfloat16 g_xlo[KB * KS * KDM];
__device__ __nv_bfloat16 g_whi[3 * KDM * KDM];
__device__ __nv_bfloat16 g_wlo[3 * KDM * KDM];
__device__ __nv_bfloat16 g_qhi[KB * KH * KS * KD];
__device__ __nv_bfloat16 g_qlo[KB * KH * KS * KD];
__device__ __nv_bfloat16 g_khi[KB * KH * KS * KD];
__device__ __nv_bfloat16 g_klo[KB * KH * KS * KD];
__device__ __nv_bfloat16 g_vhi[KB * KH * KS * KD];
__device__ __nv_bfloat16 g_vlo[KB * KH * KS * KD];

__device__ __forceinline__ uint32_t smem_u32(const void* p) {
    uint32_t a;
    asm("{ .reg .u64 t; cvta.to.shared.u64 t, %1; cvt.u32.u64 %0, t; }"
        : "=r"(a) : "l"(p));
    return a;
}

__device__ __forceinline__ void ldmx4(uint32_t& r0, uint32_t& r1, uint32_t& r2,
                                      uint32_t& r3, uint32_t addr) {
    asm volatile("ldmatrix.sync.aligned.m8n8.x4.shared.b16 {%0,%1,%2,%3}, [%4];"
                 : "=r"(r0), "=r"(r1), "=r"(r2), "=r"(r3) : "r"(addr));
}

__device__ __forceinline__ void ldmx4t(uint32_t& r0, uint32_t& r1, uint32_t& r2,
                                       uint32_t& r3, uint32_t addr) {
    asm volatile(
        "ldmatrix.sync.aligned.m8n8.x4.trans.shared.b16 {%0,%1,%2,%3}, [%4];"
        : "=r"(r0), "=r"(r1), "=r"(r2), "=r"(r3) : "r"(addr));
}

__device__ __forceinline__ void mma_bf16(float* c, const uint32_t* a,
                                         const uint32_t* b) {
    asm volatile(
        "mma.sync.aligned.m16n8k16.row.col.f32.bf16.bf16.f32 "
        "{%0,%1,%2,%3}, {%4,%5,%6,%7}, {%8,%9}, {%0,%1,%2,%3};"
        : "+f"(c[0]), "+f"(c[1]), "+f"(c[2]), "+f"(c[3])
        : "r"(a[0]), "r"(a[1]), "r"(a[2]), "r"(a[3]), "r"(b[0]), "r"(b[1]));
}

__device__ __forceinline__ void cpasync16(uint32_t saddr, const void* g) {
    asm volatile("cp.async.cg.shared.global [%0], [%1], 16;"
                 :: "r"(saddr), "l"(g) : "memory");
}
__device__ __forceinline__ void cpa_commit() {
    asm volatile("cp.async.commit_group;" ::: "memory");
}
__device__ __forceinline__ void cpa_wait1() {
    asm volatile("cp.async.wait_group 1;" ::: "memory");
}
__device__ __forceinline__ void cpa_wait2() {
    asm volatile("cp.async.wait_group 2;" ::: "memory");
}

__device__ __forceinline__ uint32_t pack_hi(float a, float b) {
    return (uint32_t)__bfloat16_as_ushort(__float2bfloat16(a)) |
           ((uint32_t)__bfloat16_as_ushort(__float2bfloat16(b)) << 16);
}
__device__ __forceinline__ uint32_t pack_lo(float a, float b) {
    float ra = a - __bfloat162float(__float2bfloat16(a));
    float rb = b - __bfloat162float(__float2bfloat16(b));
    return (uint32_t)__bfloat16_as_ushort(__float2bfloat16(ra)) |
           ((uint32_t)__bfloat16_as_ushort(__float2bfloat16(rb)) << 16);
}

// ---------------------------------------------------------------------------
// Kernel 0: split f32 -> bf16 hi + bf16 lo
// ---------------------------------------------------------------------------
__global__ __launch_bounds__(256) void cvt_split_kernel(
    const float* __restrict__ in, __nv_bfloat16* __restrict__ hi,
    __nv_bfloat16* __restrict__ lo, int n4) {
    int i = blockIdx.x * blockDim.x + threadIdx.x;
    if (i >= n4) return;
    float4 v = ((const float4*)in)[i];
    uint2 hp, lp;
    hp.x = pack_hi(v.x, v.y);
    hp.y = pack_hi(v.z, v.w);
    lp.x = pack_lo(v.x, v.y);
    lp.y = pack_lo(v.z, v.w);
    ((uint2*)hi)[i] = hp;
    ((uint2*)lo)[i] = lp;
}

// ---------------------------------------------------------------------------
// Kernel 1: QKV projection, pure-bf16 mma.sync with 3-stage cp.async pipeline.
// C[m,n] = sum_k x[m,k]*W[n,k] = Ahi*Bhi + Ahi*Blo + Alo*Bhi (fp32 acc).
// 128x128 tile, BK=32, 256 threads (8 warps, 4x2).
// Stage = Ahi,Alo,Bhi,Blo tiles of 128x32 bf16 @ 80B row stride = 40960 B.
// ---------------------------------------------------------------------------
#define ROWB 80
#define QTILE (128 * ROWB)      // 10240 B per array
#define QSTAGE (4 * QTILE)      // 40960 B
#define QNSTAGE 3
#define QSMEM (QNSTAGE * QSTAGE)  // 122880 B
#define QNK (KDM / 32)          // 32 k-chunks

__global__ __launch_bounds__(256) void qkv_mma_kernel(
    const __nv_bfloat16* __restrict__ xhi, const __nv_bfloat16* __restrict__ xlo,
    const __nv_bfloat16* __restrict__ whi, const __nv_bfloat16* __restrict__ wlo) {
    extern __shared__ char qsm[];
    const uint32_t sbase = smem_u32(qsm);

    const int tid = threadIdx.x;
    const int lane = tid & 31;
    const int wid = tid >> 5;
    const int wm = wid & 3;
    const int wn = wid >> 2;
    const int m0 = blockIdx.y * 128;
    const int n0 = blockIdx.x * 128;

    // cp.async assignment: 8 chunks/thread covering 4 arrays x 128 rows x 4 segs
    const __nv_bfloat16* gA[4];
    gA[0] = xhi + (size_t)m0 * KDM;
    gA[1] = xlo + (size_t)m0 * KDM;
    gA[2] = whi + (size_t)n0 * KDM;
    gA[3] = wlo + (size_t)n0 * KDM;

#define QISSUE(s)                                                             \
    {                                                                         \
        const int k0_ = (s) * 32;                                             \
        char* sb_ = qsm + ((s) % QNSTAGE) * QSTAGE;                           \
        _Pragma("unroll") for (int t = 0; t < 8; ++t) {                       \
            int idx = tid + t * 256;                                          \
            int arr = idx >> 9;                                               \
            int rem = idx & 511;                                              \
            int row = rem >> 2, seg = rem & 3;                                \
            cpasync16(smem_u32(sb_ + arr * QTILE + row * ROWB + seg * 16),    \
                      gA[arr] + (size_t)row * KDM + k0_ + seg * 8);           \
        }                                                                     \
    }

    QISSUE(0); cpa_commit();
    QISSUE(1); cpa_commit();
    QISSUE(2); cpa_commit();

    float acc[2][8][4] = {};
    const int q = lane >> 3, roff = lane & 7;

    for (int s = 0; s < QNK; ++s) {
        cpa_wait2();
        __syncthreads();

        const uint32_t sb = sbase + (s % QNSTAGE) * QSTAGE;
        const uint32_t sA_hi = sb, sA_lo = sb + QTILE;
        const uint32_t sB_hi = sb + 2 * QTILE, sB_lo = sb + 3 * QTILE;

#pragma unroll
        for (int ks = 0; ks < 2; ++ks) {
            uint32_t ahi[2][4], alo[2][4], bhi[8][2], blo[8][2];
            const uint32_t aoff =
                (uint32_t)(wm * 32 + (q & 1) * 8 + roff) * ROWB +
                (ks * 16 + (q >> 1) * 8) * 2;
#pragma unroll
            for (int mt = 0; mt < 2; ++mt) {
                ldmx4(ahi[mt][0], ahi[mt][1], ahi[mt][2], ahi[mt][3],
                      sA_hi + aoff + mt * 16 * ROWB);
                ldmx4(alo[mt][0], alo[mt][1], alo[mt][2], alo[mt][3],
                      sA_lo + aoff + mt * 16 * ROWB);
            }
            const uint32_t boff =
                (uint32_t)(wn * 64 + (q >> 1) * 8 + roff) * ROWB +
                (ks * 16 + (q & 1) * 8) * 2;
#pragma unroll
            for (int p = 0; p < 4; ++p) {
                ldmx4(bhi[2 * p][0], bhi[2 * p][1], bhi[2 * p + 1][0],
                      bhi[2 * p + 1][1], sB_hi + boff + p * 16 * ROWB);
                ldmx4(blo[2 * p][0], blo[2 * p][1], blo[2 * p + 1][0],
                      blo[2 * p + 1][1], sB_lo + boff + p * 16 * ROWB);
            }
#pragma unroll
            for (int mt = 0; mt < 2; ++mt)
#pragma unroll
                for (int nt = 0; nt < 8; ++nt) {
                    mma_bf16(acc[mt][nt], ahi[mt], bhi[nt]);
                    mma_bf16(acc[mt][nt], ahi[mt], blo[nt]);
                    mma_bf16(acc[mt][nt], alo[mt], bhi[nt]);
                }
        }
        __syncthreads();
        if (s + QNSTAGE < QNK) QISSUE(s + QNSTAGE);
        cpa_commit();
    }

    // Epilogue: bf16 hi/lo split scatter (Q gets KSCALE folded in)
#pragma unroll
    for (int mt = 0; mt < 2; ++mt) {
#pragma unroll
        for (int nt = 0; nt < 8; ++nt) {
            int n = n0 + wn * 64 + nt * 8 + (lane & 3) * 2;
            int three = n >> 10;
            int h = (n >> 6) & 15;
            int d = n & 63;
            __nv_bfloat16* dhi =
                (three == 0) ? g_qhi : (three == 1) ? g_khi : g_vhi;
            __nv_bfloat16* dlo =
                (three == 0) ? g_qlo : (three == 1) ? g_klo : g_vlo;
            float sc = (three == 0) ? KSCALE : 1.0f;
            int m = m0 + wm * 32 + mt * 16 + (lane >> 2);
            int bb = m >> 11, ss = m & 2047;
            size_t off = ((size_t)(bb * KH + h) * KS + ss) * KD + d;
            float v0 = acc[mt][nt][0] * sc, v1 = acc[mt][nt][1] * sc;
            *(uint32_t*)(dhi + off) = pack_hi(v0, v1);
            *(uint32_t*)(dlo + off) = pack_lo(v0, v1);
            float v2 = acc[mt][nt][2] * sc, v3 = acc[mt][nt][3] * sc;
            *(uint32_t*)(dhi + off + 8 * KD) = pack_hi(v2, v3);
            *(uint32_t*)(dlo + off + 8 * KD) = pack_lo(v2, v3);
        }
    }
}

// ---------------------------------------------------------------------------
// Kernel 2: flash attention, mma.sync bf16 hi/lo + cp.async double buffering.
// (unchanged from R5)
// ---------------------------------------------------------------------------
#define FROWB 144
#define FTILE (64 * FROWB)
#define FSTAGE (4 * FTILE)
#define FSMEM (2 * FSTAGE)
#define FNT (KS / 64)

__global__ __launch_bounds__(128, 3) void flash_mma_kernel(
    const uint32_t* __restrict__ mask, float* __restrict__ out) {
    extern __shared__ char fsm[];
    const uint32_t dynb = smem_u32(fsm);

    const int tid = threadIdx.x;
    const int lane = tid & 31;
    const int w = tid >> 5;
    const int qt = blockIdx.x;
    const int h = blockIdx.y;
    const int b = blockIdx.z;
    const int q0 = qt * 64;

    const size_t headoff = ((size_t)(b * KH + h) * KS) * KD;

#pragma unroll
    for (int t = 0; t < 4; ++t) {
        int idx = tid + t * 128;
        int row = idx >> 3, seg = idx & 7;
        uint32_t so = row * FROWB + seg * 16;
        size_t go = headoff + (size_t)(q0 + row) * KD + seg * 8;
        *(uint4*)(fsm + so) = *(const uint4*)(g_qhi + go);
        *(uint4*)(fsm + FTILE + so) = *(const uint4*)(g_qlo + go);
    }
    __syncthreads();

    uint32_t qfh[4][4], qfl[4][4];
    {
        int arow = 16 * w + (lane & 7) + ((lane >> 3) & 1) * 8;
#pragma unroll
        for (int t = 0; t < 4; ++t) {
            uint32_t off = (uint32_t)arow * FROWB + t * 32 + (lane >> 4) * 16;
            ldmx4(qfh[t][0], qfh[t][1], qfh[t][2], qfh[t][3], dynb + off);
            ldmx4(qfl[t][0], qfl[t][1], qfl[t][2], qfl[t][3],
                  dynb + FTILE + off);
        }
    }
    __syncthreads();

#define ISSUE_TILE(kt, buf)                                                   \
    {                                                                         \
        _Pragma("unroll") for (int t = 0; t < 4; ++t) {                       \
            int idx = tid + t * 128;                                          \
            int row = idx >> 3, seg = idx & 7;                                \
            uint32_t so = dynb + (buf) * FSTAGE + row * FROWB + seg * 16;     \
            size_t go = headoff + (size_t)((kt) * 64 + row) * KD + seg * 8;   \
            cpasync16(so, g_khi + go);                                        \
            cpasync16(so + FTILE, g_klo + go);                                \
            cpasync16(so + 2 * FTILE, g_vhi + go);                            \
            cpasync16(so + 3 * FTILE, g_vlo + go);                            \
        }                                                                     \
    }

    ISSUE_TILE(0, 0);
    cpa_commit();
    ISSUE_TILE(1, 1);
    cpa_commit();

    const int rq = lane >> 2, cq = lane & 3;
    const int bB_row = (lane & 7) + ((lane >> 4) & 1) * 8;
    const int bB_seg = (lane >> 3) & 1;
    const int vB_row = (lane & 7) + ((lane >> 3) & 1) * 8;
    const int vB_seg = (lane >> 4) & 1;

    float o[8][4] = {};
    float m0 = __int_as_float(0xff800000), m1 = m0;
    float l0 = 0.0f, l1 = 0.0f;

    const uint32_t* mr0 =
        mask + ((size_t)(b * KS + q0 + 16 * w + rq) * KH + h) * KS + 2 * cq;
    const uint32_t* mr1 = mr0 + (size_t)8 * KH * KS;

    for (int kt = 0; kt < FNT; ++kt) {
        cpa_wait1();
        __syncthreads();

        const uint32_t sK = dynb + (kt & 1) * FSTAGE;
        const uint32_t sKl = sK + FTILE;
        const uint32_t sV = sK + 2 * FTILE;
        const uint32_t sVl = sK + 3 * FTILE;

        const uint32_t* mk0 = mr0 + kt * 64;
        const uint32_t* mk1 = mr1 + kt * 64;
        uint32_t mbits = 0;
#pragma unroll
        for (int j = 0; j < 8; ++j) {
            uint2 a = *(const uint2*)(mk0 + 8 * j);
            uint2 c = *(const uint2*)(mk1 + 8 * j);
            mbits |= (a.x ? 1u : 0u) << (4 * j);
            mbits |= (a.y ? 2u : 0u) << (4 * j);
            mbits |= (c.x ? 4u : 0u) << (4 * j);
            mbits |= (c.y ? 8u : 0u) << (4 * j);
        }

        float s[8][4] = {};
#pragma unroll
        for (int t = 0; t < 4; ++t) {
            uint32_t bh[8][2], bl[8][2];
#pragma unroll
            for (int jp = 0; jp < 4; ++jp) {
                uint32_t off = (uint32_t)(16 * jp + bB_row) * FROWB +
                               (2 * t + bB_seg) * 16;
                ldmx4(bh[2 * jp][0], bh[2 * jp][1], bh[2 * jp + 1][0],
                      bh[2 * jp + 1][1], sK + off);
                ldmx4(bl[2 * jp][0], bl[2 * jp][1], bl[2 * jp + 1][0],
                      bl[2 * jp + 1][1], sKl + off);
            }
#pragma unroll
            for (int j = 0; j < 8; ++j) {
                mma_bf16(s[j], qfh[t], bh[j]);
                mma_bf16(s[j], qfh[t], bl[j]);
                mma_bf16(s[j], qfl[t], bh[j]);
            }
        }

#pragma unroll
        for (int j = 0; j < 8; ++j) {
            uint32_t mj = mbits >> (4 * j);
            s[j][0] = (mj & 1) ? s[j][0] : KMASKFILL;
            s[j][1] = (mj & 2) ? s[j][1] : KMASKFILL;
            s[j][2] = (mj & 4) ? s[j][2] : KMASKFILL;
            s[j][3] = (mj & 8) ? s[j][3] : KMASKFILL;
        }

        float t0 = __int_as_float(0xff800000), t1 = t0;
#pragma unroll
        for (int j = 0; j < 8; ++j) {
            t0 = fmaxf(t0, fmaxf(s[j][0], s[j][1]));
            t1 = fmaxf(t1, fmaxf(s[j][2], s[j][3]));
        }
        t0 = fmaxf(t0, __shfl_xor_sync(0xffffffffu, t0, 1));
        t0 = fmaxf(t0, __shfl_xor_sync(0xffffffffu, t0, 2));
        t1 = fmaxf(t1, __shfl_xor_sync(0xffffffffu, t1, 1));
        t1 = fmaxf(t1, __shfl_xor_sync(0xffffffffu, t1, 2));
        float mn0 = fmaxf(m0, t0), mn1 = fmaxf(m1, t1);
        float c0 = __expf(m0 - mn0), c1 = __expf(m1 - mn1);
        m0 = mn0;
        m1 = mn1;
        float rs0 = 0.0f, rs1 = 0.0f;
#pragma unroll
        for (int j = 0; j < 8; ++j) {
            s[j][0] = __expf(s[j][0] - mn0);
            s[j][1] = __expf(s[j][1] - mn0);
            s[j][2] = __expf(s[j][2] - mn1);
            s[j][3] = __expf(s[j][3] - mn1);
            rs0 += s[j][0] + s[j][1];
            rs1 += s[j][2] + s[j][3];
        }
        rs0 += __shfl_xor_sync(0xffffffffu, rs0, 1);
        rs0 += __shfl_xor_sync(0xffffffffu, rs0, 2);
        rs1 += __shfl_xor_sync(0xffffffffu, rs1, 1);
        rs1 += __shfl_xor_sync(0xffffffffu, rs1, 2);
        l0 = l0 * c0 + rs0;
        l1 = l1 * c1 + rs1;
#pragma unroll
        for (int nd = 0; nd < 8; ++nd) {
            o[nd][0] *= c0;
            o[nd][1] *= c0;
            o[nd][2] *= c1;
            o[nd][3] *= c1;
        }

        uint32_t ph[4][4], pl[4][4];
#pragma unroll
        for (int t = 0; t < 4; ++t) {
            ph[t][0] = pack_hi(s[2 * t][0], s[2 * t][1]);
            ph[t][1] = pack_hi(s[2 * t][2], s[2 * t][3]);
            ph[t][2] = pack_hi(s[2 * t + 1][0], s[2 * t + 1][1]);
            ph[t][3] = pack_hi(s[2 * t + 1][2], s[2 * t + 1][3]);
            pl[t][0] = pack_lo(s[2 * t][0], s[2 * t][1]);
            pl[t][1] = pack_lo(s[2 * t][2], s[2 * t][3]);
            pl[t][2] = pack_lo(s[2 * t + 1][0], s[2 * t + 1][1]);
            pl[t][3] = pack_lo(s[2 * t + 1][2], s[2 * t + 1][3]);
        }

#pragma unroll
        for (int t = 0; t < 4; ++t) {
            uint32_t vh[8][2], vl[8][2];
#pragma unroll
            for (int np = 0; np < 4; ++np) {
                uint32_t off = (uint32_t)(16 * t + vB_row) * FROWB +
                               (2 * np + vB_seg) * 16;
                ldmx4t(vh[2 * np][0], vh[2 * np][1], vh[2 * np + 1][0],
                       vh[2 * np + 1][1], sV + off);
                ldmx4t(vl[2 * np][0], vl[2 * np][1], vl[2 * np + 1][0],
                       vl[2 * np + 1][1], sVl + off);
            }
#pragma unroll
            for (int nd = 0; nd < 8; ++nd) {
                mma_bf16(o[nd], ph[t], vh[nd]);
                mma_bf16(o[nd], ph[t], vl[nd]);
                mma_bf16(o[nd], pl[t], vh[nd]);
            }
        }
        __syncthreads();

        if (kt + 2 < FNT) ISSUE_TILE(kt + 2, kt & 1);
        cpa_commit();
    }

    float inv0 = 1.0f / l0, inv1 = 1.0f / l1;
    const int row0 = q0 + 16 * w + rq;
#pragma unroll
    for (int nd = 0; nd < 8; ++nd) {
        int d = 8 * nd + 2 * cq;
        float* p0 = out + (size_t)(b * KS + row0) * KDM + h * KD + d;
        *(float2*)p0 = make_float2(o[nd][0] * inv0, o[nd][1] * inv0);
        float* p1 = p0 + (size_t)8 * KDM;
        *(float2*)p1 = make_float2(o[nd][2] * inv1, o[nd][3] * inv1);
    }
}

extern "C" void kernel_launch(void* const* d_in, const int* in_sizes, int n_in,
                              void* d_out, int out_size) {
    const float* x = (const float*)d_in[0];
    const float* w = (const float*)d_in[1];
    const uint32_t* mask = (const uint32_t*)d_in[2];
    float* out = (float*)d_out;

    __nv_bfloat16 *xhi, *xlo, *whi, *wlo;
    cudaGetSymbolAddress((void**)&xhi, g_xhi);
    cudaGetSymbolAddress((void**)&xlo, g_xlo);
    cudaGetSymbolAddress((void**)&whi, g_whi);
    cudaGetSymbolAddress((void**)&wlo, g_wlo);

    cudaFuncSetAttribute(qkv_mma_kernel,
                         cudaFuncAttributeMaxDynamicSharedMemorySize, QSMEM);
    cudaFuncSetAttribute(flash_mma_kernel,
                         cudaFuncAttributeMaxDynamicSharedMemorySize, FSMEM);

    const int nx4 = KB * KS * KDM / 4;
    const int nw4 = 3 * KDM * KDM / 4;
    cvt_split_kernel<<<(nx4 + 255) / 256, 256>>>(x, xhi, xlo, nx4);
    cvt_split_kernel<<<(nw4 + 255) / 256, 256>>>(w, whi, wlo, nw4);

    dim3 g1(3 * KDM / 128, KB * KS / 128);  // (24, 32)
    qkv_mma_kernel<<<g1, 256, QSMEM>>>(xhi, xlo, whi, wlo);

    dim3 g2(KS / 64, KH, KB);  // (32, 16, 2)
    flash_mma_kernel<<<g2, 128, FSMEM>>>(mask, out);
}